// round 6
// baseline (speedup 1.0000x reference)
#include <cuda_runtime.h>

#define NS 25
#define NC 80
#define CD (NC*NC)          // 6400
#define BATCH 64
#define TIME 400
#define BT (BATCH*TIME)     // 25600

#define RPT 16              // bt rows per tile
#define RPTH 8              // rows per thread (2 row-groups)
#define NTILES (BT / RPT)   // 1600
#define CTHREADS 320
#define COLT 160            // column-threads; 160 * 8 floats = 1280 cols/block
#define YBLKS 58            // 5 * 58 = 290 blocks = 2/SM, single wave

__device__ __forceinline__ void ffma2(unsigned long long &acc,
                                      unsigned long long a,
                                      unsigned long long b) {
    asm("fma.rn.f32x2 %0, %1, %2, %0;" : "+l"(acc) : "l"(a), "l"(b));
}

__device__ __forceinline__ float softplus_f(float x) { return log1pf(expf(x)); }

// ---------------------------------------------------------------------------
// Persistent fused kernel, grid (5, YBLKS), 320 threads, 2 blocks/SM.
// Thread: grp = tid/160 -> rows grp*8..grp*8+7; ct = tid%160 -> 8 floats at
// col8 = bx*160+ct. Per j: 2 LDG.128 (D) + 4 LDS.128 (a-pairs) -> 32 FFMA2.
// ---------------------------------------------------------------------------
__global__ __launch_bounds__(CTHREADS, 2)
void fused_kernel(const float* __restrict__ alpha,
                  const float* __restrict__ mu,
                  const float* __restrict__ D,
                  const float* __restrict__ asc,
                  float* __restrict__ m_out,
                  float* __restrict__ C)
{
    __shared__ float scale_s[NS];
    __shared__ __align__(16) unsigned long long a2s[NS * RPT];  // [j][r] {a,a}
    __shared__ float mu_s[NS * NC];                             // x==0 only

    const int tid = threadIdx.x;
    const bool do_m = (blockIdx.x == 0);

    if (tid < NS) scale_s[tid] = softplus_f(asc[tid]);
    if (do_m) {
        for (int i = tid; i < NS * NC; i += CTHREADS) mu_s[i] = mu[i];
    }

    const int grp = tid / COLT;               // 0 or 1 (warps don't straddle)
    const int ct  = tid - grp * COLT;         // 0..159
    const int r0  = grp * RPTH;
    const int col8 = blockIdx.x * COLT + ct;  // 8-float column unit, 0..799
    const char* Dbase = reinterpret_cast<const char*>(D) + (size_t)col8 * 32;

    // alpha prefetch: tile has RPT*NS = 400 entries; i = r*NS + j
    const int i0 = tid;
    const int i1 = tid + CTHREADS;
    const int j_0 = i0 % NS, rr0 = i0 / NS;
    const int j_1 = i1 % NS, rr1 = i1 / NS;
    const bool has1 = (i1 < RPT * NS);

    int yt = blockIdx.y;
    float pa0 = 0.f, pa1 = 0.f;
    if (yt < NTILES) {
        const float* ap = alpha + (size_t)yt * (RPT * NS);
        pa0 = ap[i0];
        if (has1) pa1 = ap[i1];
    }

    for (; yt < NTILES; yt += YBLKS) {
        const int bt0 = yt * RPT;

        __syncthreads();   // prior tile's a2s readers done (and scale_s, iter 0)
        {
            const float v = pa0 * scale_s[j_0];
            float2 p = make_float2(v, v);
            a2s[j_0 * RPT + rr0] = *reinterpret_cast<unsigned long long*>(&p);
        }
        if (has1) {
            const float v = pa1 * scale_s[j_1];
            float2 p = make_float2(v, v);
            a2s[j_1 * RPT + rr1] = *reinterpret_cast<unsigned long long*>(&p);
        }
        __syncthreads();

        // prefetch next tile's alpha (overlaps compute)
        if (yt + YBLKS < NTILES) {
            const float* ap = alpha + (size_t)(yt + YBLKS) * (RPT * NS);
            pa0 = ap[i0];
            if (has1) pa1 = ap[i1];
        }

        // -------- C tile: 8 rows x 8 cols per thread (64 acc regs) --------
        unsigned long long acc[RPTH][4];
        #pragma unroll
        for (int r = 0; r < RPTH; r++)
            #pragma unroll
            for (int q = 0; q < 4; q++) acc[r][q] = 0ull;

        #pragma unroll 5
        for (int j = 0; j < NS; j++) {
            const char* dp = Dbase + (size_t)j * (CD * 4);
            const ulonglong2 d0 = *reinterpret_cast<const ulonglong2*>(dp);
            const ulonglong2 d1 = *reinterpret_cast<const ulonglong2*>(dp + 16);
            #pragma unroll
            for (int p = 0; p < RPTH / 2; p++) {
                const ulonglong2 aa =
                    *reinterpret_cast<const ulonglong2*>(&a2s[j * RPT + r0 + 2 * p]);
                const int ra = 2 * p, rb = 2 * p + 1;
                ffma2(acc[ra][0], d0.x, aa.x);
                ffma2(acc[ra][1], d0.y, aa.x);
                ffma2(acc[ra][2], d1.x, aa.x);
                ffma2(acc[ra][3], d1.y, aa.x);
                ffma2(acc[rb][0], d0.x, aa.y);
                ffma2(acc[rb][1], d0.y, aa.y);
                ffma2(acc[rb][2], d1.x, aa.y);
                ffma2(acc[rb][3], d1.y, aa.y);
            }
        }

        float* Cbase = C + (size_t)(bt0 + r0) * CD + (size_t)col8 * 8;
        #pragma unroll
        for (int r = 0; r < RPTH; r++) {
            ulonglong2 u0, u1;
            u0.x = acc[r][0]; u0.y = acc[r][1];
            u1.x = acc[r][2]; u1.y = acc[r][3];
            float* row = Cbase + (size_t)r * CD;
            __stcs(reinterpret_cast<float4*>(row),
                   *reinterpret_cast<float4*>(&u0));
            __stcs(reinterpret_cast<float4*>(row) + 1,
                   *reinterpret_cast<float4*>(&u1));
        }

        // ---------------- m tile (x==0 blocks only) ----------------
        if (do_m) {
            #pragma unroll
            for (int o = tid; o < RPT * NC; o += CTHREADS) {
                const int r = o / NC, c = o % NC;
                float s = 0.0f;
                #pragma unroll
                for (int j = 0; j < NS; j++) {
                    const float a = reinterpret_cast<const float2*>(&a2s[j * RPT + r])->x;
                    s = fmaf(a, mu_s[j * NC + c], s);
                }
                __stcs(&m_out[(size_t)(bt0 + r) * NC + c], s);
            }
        }
    }
}

extern "C" void kernel_launch(void* const* d_in, const int* in_sizes, int n_in,
                              void* d_out, int out_size)
{
    const float* alpha = (const float*)d_in[0];   // [64,400,25]
    const float* mu    = (const float*)d_in[1];   // [25,80]
    const float* D     = (const float*)d_in[2];   // [25,80,80]
    const float* asc   = (const float*)d_in[3];   // [25]

    float* out = (float*)d_out;
    float* m_out = out;                  // [64,400,80]
    float* c_out = out + (BT * NC);      // [64,400,80,80]

    fused_kernel<<<dim3(5, YBLKS), CTHREADS>>>(alpha, mu, D, asc, m_out, c_out);
}

// round 9
// speedup vs baseline: 1.0968x; 1.0968x over previous
#include <cuda_runtime.h>
#include <cstdint>

#define NS 25
#define NC 80
#define CD 6400
#define BT 25600

#define MTB 128              // block tile rows
#define NTB 128              // block tile cols
#define KP 32                // padded K
#define STR 132              // smem row stride (floats), k-plane stride
#define THREADS 128
#define NXB (CD / NTB)       // 50
#define NYB (BT / MTB)       // 200

// dyn smem: AH | AL | BH | BL, each 32 x 132 floats
#define SM_FLOATS (4 * KP * STR)          // 16896 floats = 67584 B

__device__ __forceinline__ void mma_tf32(float* acc, const uint32_t* a,
                                         uint32_t b0, uint32_t b1) {
    asm volatile(
        "mma.sync.aligned.m16n8k8.row.col.f32.tf32.tf32.f32 "
        "{%0,%1,%2,%3}, {%4,%5,%6,%7}, {%8,%9}, {%0,%1,%2,%3};"
        : "+f"(acc[0]), "+f"(acc[1]), "+f"(acc[2]), "+f"(acc[3])
        : "r"(a[0]), "r"(a[1]), "r"(a[2]), "r"(a[3]), "r"(b0), "r"(b1));
}
__device__ __forceinline__ uint32_t f2tf32(float v) {
    uint32_t r;
    asm("cvt.rna.tf32.f32 %0, %1;" : "=r"(r) : "f"(v));
    return r;
}

// ---------------------------------------------------------------------------
// C[m][n] = sum_j (alpha[m][j]*softplus(asc[j])) * D[j][n]
// Block: 128x128 tile. Warp w: rows w*32..w*32+31, all 128 cols.
// a-fragments register-resident (hi+lo); b streamed from smem.
// ---------------------------------------------------------------------------
__global__ __launch_bounds__(THREADS, 3)
void tc_kernel(const float* __restrict__ alpha,
               const float* __restrict__ D,
               const float* __restrict__ asc,
               float* __restrict__ C)
{
    extern __shared__ float sm[];
    float* AH = sm;
    float* AL = sm + KP * STR;
    float* BH = sm + 2 * KP * STR;
    float* BL = sm + 3 * KP * STR;
    __shared__ float scale_s[NS];

    const int tid = threadIdx.x;
    const int m0 = blockIdx.y * MTB;
    const int nb = blockIdx.x * NTB;

    if (tid < NS) scale_s[tid] = log1pf(expf(asc[tid]));

    // zero smem (covers k = 25..31 padding)
    {
        float4* p = reinterpret_cast<float4*>(sm);
        for (int i = tid; i < SM_FLOATS / 4; i += THREADS)
            p[i] = make_float4(0.f, 0.f, 0.f, 0.f);
    }
    __syncthreads();

    // A tile: 128 rows x 25 -> AH/AL [k][r]
    {
        const float* ap = alpha + (size_t)m0 * NS;
        for (int i = tid; i < MTB * NS; i += THREADS) {
            const int r = i / NS, j = i - r * NS;
            const float v = ap[i] * scale_s[j];
            const uint32_t hv = f2tf32(v);
            const float hf = __uint_as_float(hv);
            AH[j * STR + r] = hf;
            AL[j * STR + r] = __uint_as_float(f2tf32(v - hf));
        }
    }
    // B tile: 25 x 128 -> BH/BL [k][n]
    for (int i = tid; i < NS * NTB; i += THREADS) {
        const int j = i / NTB, n = i - j * NTB;
        const float v = D[(size_t)j * CD + nb + n];
        const uint32_t hv = f2tf32(v);
        const float hf = __uint_as_float(hv);
        BH[j * STR + n] = hf;
        BL[j * STR + n] = __uint_as_float(f2tf32(v - hf));
    }
    __syncthreads();

    const int w = tid >> 5, lane = tid & 31;
    const int grp = lane >> 2, kk = lane & 3;

    // a-fragments: 2 m-steps x 4 k-groups x 4 regs, hi + lo (64 regs)
    uint32_t ah[2][4][4], al[2][4][4];
    #pragma unroll
    for (int m = 0; m < 2; m++) {
        const int rb = w * 32 + m * 16 + grp;
        #pragma unroll
        for (int g = 0; g < 4; g++) {
            const int k0 = (g * 8 + kk) * STR, k1 = k0 + 4 * STR;
            ah[m][g][0] = __float_as_uint(AH[k0 + rb]);
            ah[m][g][1] = __float_as_uint(AH[k0 + rb + 8]);
            ah[m][g][2] = __float_as_uint(AH[k1 + rb]);
            ah[m][g][3] = __float_as_uint(AH[k1 + rb + 8]);
            al[m][g][0] = __float_as_uint(AL[k0 + rb]);
            al[m][g][1] = __float_as_uint(AL[k0 + rb + 8]);
            al[m][g][2] = __float_as_uint(AL[k1 + rb]);
            al[m][g][3] = __float_as_uint(AL[k1 + rb + 8]);
        }
    }

    #pragma unroll
    for (int sp = 0; sp < 8; sp++) {
        float acc[2][2][4];
        #pragma unroll
        for (int m = 0; m < 2; m++)
            #pragma unroll
            for (int s = 0; s < 2; s++)
                #pragma unroll
                for (int q = 0; q < 4; q++) acc[m][s][q] = 0.f;

        #pragma unroll
        for (int g = 0; g < 4; g++) {
            const int k0 = (g * 8 + kk) * STR, k1 = k0 + 4 * STR;
            const int n0 = sp * 8 + grp, n1 = n0 + 64;
            const uint32_t b0h  = __float_as_uint(BH[k0 + n0]);
            const uint32_t b1h  = __float_as_uint(BH[k1 + n0]);
            const uint32_t b0l  = __float_as_uint(BL[k0 + n0]);
            const uint32_t b1l  = __float_as_uint(BL[k1 + n0]);
            const uint32_t b0h2 = __float_as_uint(BH[k0 + n1]);
            const uint32_t b1h2 = __float_as_uint(BH[k1 + n1]);
            const uint32_t b0l2 = __float_as_uint(BL[k0 + n1]);
            const uint32_t b1l2 = __float_as_uint(BL[k1 + n1]);
            #pragma unroll
            for (int m = 0; m < 2; m++) {
                mma_tf32(acc[m][0], ah[m][g], b0h, b1h);
                mma_tf32(acc[m][1], ah[m][g], b0h2, b1h2);
                mma_tf32(acc[m][0], al[m][g], b0h, b1h);
                mma_tf32(acc[m][1], al[m][g], b0h2, b1h2);
                mma_tf32(acc[m][0], ah[m][g], b0l, b1l);
                mma_tf32(acc[m][1], ah[m][g], b0l2, b1l2);
            }
        }

        #pragma unroll
        for (int m = 0; m < 2; m++) {
            const size_t r0 = (size_t)(m0 + w * 32 + m * 16 + grp);
            #pragma unroll
            for (int s = 0; s < 2; s++) {
                const int col = nb + sp * 8 + s * 64 + kk * 2;
                __stcs(reinterpret_cast<float2*>(C + r0 * CD + col),
                       make_float2(acc[m][s][0], acc[m][s][1]));
                __stcs(reinterpret_cast<float2*>(C + (r0 + 8) * CD + col),
                       make_float2(acc[m][s][2], acc[m][s][3]));
            }
        }
    }
}

// ---------------------------------------------------------------------------
// m_t = A @ mu (tiny)
// ---------------------------------------------------------------------------
__global__ __launch_bounds__(256)
void m_kernel(const float* __restrict__ alpha,
              const float* __restrict__ mu,
              const float* __restrict__ asc,
              float* __restrict__ m)
{
    __shared__ float mu_s[NS * NC];
    __shared__ float a_s[16 * NS];
    __shared__ float scale_s[NS];

    const int tid = threadIdx.x;
    if (tid < NS) scale_s[tid] = log1pf(expf(asc[tid]));
    __syncthreads();

    for (int i = tid; i < NS * NC; i += 256) mu_s[i] = mu[i];

    const int bt0 = blockIdx.x * 16;
    for (int i = tid; i < 16 * NS; i += 256) {
        const int r = i / NS, j = i % NS;
        a_s[i] = alpha[(bt0 + r) * NS + j] * scale_s[j];
    }
    __syncthreads();

    for (int o = tid; o < 16 * NC; o += 256) {
        const int r = o / NC, c = o % NC;
        float s = 0.0f;
        #pragma unroll
        for (int j = 0; j < NS; j++) s = fmaf(a_s[r * NS + j], mu_s[j * NC + c], s);
        m[(size_t)(bt0 + r) * NC + c] = s;
    }
}

extern "C" void kernel_launch(void* const* d_in, const int* in_sizes, int n_in,
                              void* d_out, int out_size)
{
    const float* alpha = (const float*)d_in[0];   // [64,400,25]
    const float* mu    = (const float*)d_in[1];   // [25,80]
    const float* D     = (const float*)d_in[2];   // [25,80,80]
    const float* asc   = (const float*)d_in[3];   // [25]

    float* out   = (float*)d_out;
    float* m_out = out;                 // [64,400,80]
    float* c_out = out + (BT * NC);     // [64,400,80,80]

    static int smem_set = 0;
    if (!smem_set) {
        cudaFuncSetAttribute(tc_kernel, cudaFuncAttributeMaxDynamicSharedMemorySize,
                             SM_FLOATS * 4);
        smem_set = 1;
    }

    m_kernel<<<BT / 16, 256>>>(alpha, mu, asc, m_out);
    tc_kernel<<<dim3(NXB, NYB), THREADS, SM_FLOATS * 4>>>(alpha, D, asc, c_out);
}

// round 11
// speedup vs baseline: 1.5653x; 1.4271x over previous
#include <cuda_runtime.h>
#include <cstdint>

#define NS 25
#define NC 80
#define CD 6400
#define BT 25600

#define MTB 128              // M rows per tile
#define NTB 128              // N cols per block stripe
#define THREADS 128
#define NXB 50               // 6400/128
#define NYB 11               // 50*11 = 550 blocks <= 148*4 (one wave)
#define MTILES 200           // 25600/128

#define PL 16                // k2 planes (K padded to 32)
#define PSTR 132             // uint2 elements per plane (conflict-free)

__device__ __forceinline__ uint16_t f2bf(float v) {
    uint16_t r;
    asm("cvt.rn.bf16.f32 %0, %1;" : "=h"(r) : "f"(v));
    return r;
}
__device__ __forceinline__ float bf2f(uint16_t h) {
    return __uint_as_float((uint32_t)h << 16);
}
__device__ __forceinline__ void mma_bf16(float* acc, const uint32_t* a,
                                         uint32_t b0, uint32_t b1) {
    asm volatile(
        "mma.sync.aligned.m16n8k16.row.col.f32.bf16.bf16.f32 "
        "{%0,%1,%2,%3}, {%4,%5,%6,%7}, {%8,%9}, {%0,%1,%2,%3};"
        : "+f"(acc[0]), "+f"(acc[1]), "+f"(acc[2]), "+f"(acc[3])
        : "r"(a[0]), "r"(a[1]), "r"(a[2]), "r"(a[3]), "r"(b0), "r"(b1));
}

// ---------------------------------------------------------------------------
// C = A @ D_flat via bf16 3-term split (Ah*Bh + Al*Bh + Ah*Bl).
// Persistent N-stripe blocks: B split once; loop over M tiles.
// smem planes: uint2 {hi_pair, lo_pair}; pair = packed bf16x2 {k even, k odd}.
// ---------------------------------------------------------------------------
__global__ __launch_bounds__(THREADS, 4)
void tc_kernel(const float* __restrict__ alpha,
               const float* __restrict__ D,
               const float* __restrict__ asc,
               float* __restrict__ C)
{
    __shared__ uint2 AHL[PL * PSTR];    // 16.9 KB: A planes [k2][row]
    __shared__ uint2 BHL[PL * PSTR];    // 16.9 KB: B planes [k2][col]
    __shared__ float scale_s[32];

    const int tid = threadIdx.x;
    if (tid < NS) scale_s[tid] = log1pf(expf(asc[tid]));

    // zero both plane arrays once (covers k=25..31 padding)
    {
        uint4* z = reinterpret_cast<uint4*>(AHL);   // AHL,BHL adjacent? not guaranteed
        for (int i = tid; i < (PL * PSTR) / 2; i += THREADS) z[i] = make_uint4(0,0,0,0);
        uint4* z2 = reinterpret_cast<uint4*>(BHL);
        for (int i = tid; i < (PL * PSTR) / 2; i += THREADS) z2[i] = make_uint4(0,0,0,0);
    }
    __syncthreads();

    const int nb = blockIdx.x * NTB;

    // ---- B split (once): element (k, n) -> plane k>>1, col n ----
    for (int i = tid; i < NS * NTB; i += THREADS) {
        const int k = i >> 7, n = i & 127;          // coalesced over n
        const float v = D[(size_t)k * CD + nb + n];
        const uint16_t h = f2bf(v);
        const uint16_t l = f2bf(v - bf2f(h));
        char* base = reinterpret_cast<char*>(&BHL[(k >> 1) * PSTR + n]);
        *reinterpret_cast<uint16_t*>(base + (k & 1) * 2)     = h;
        *reinterpret_cast<uint16_t*>(base + 4 + (k & 1) * 2) = l;
    }

    const int w = tid >> 5, lane = tid & 31;
    const int grp = lane >> 2, kk = lane & 3;

    for (int mt = blockIdx.y; mt < MTILES; mt += NYB) {
        const int m0 = mt * MTB;

        __syncthreads();   // prior iter's a-frag loads done; 1st iter: B+zero visible
        // ---- A split: element i -> (r = i/25, k = i%25), coalesced LDG ----
        {
            const float* ap = alpha + (size_t)m0 * NS;
            #pragma unroll
            for (int t = 0; t < (MTB * NS) / THREADS; t++) {
                const int i = tid + t * THREADS;
                const int r = i / NS, k = i - r * NS;
                const float v = ap[i] * scale_s[k];
                const uint16_t h = f2bf(v);
                const uint16_t l = f2bf(v - bf2f(h));
                char* base = reinterpret_cast<char*>(&AHL[(k >> 1) * PSTR + r]);
                *reinterpret_cast<uint16_t*>(base + (k & 1) * 2)     = h;
                *reinterpret_cast<uint16_t*>(base + 4 + (k & 1) * 2) = l;
            }
        }
        __syncthreads();

        // ---- a-fragments (hi+lo) register-resident: 32 regs ----
        uint32_t ah[2][2][4], al[2][2][4];
        #pragma unroll
        for (int m = 0; m < 2; m++) {
            const int rb = w * 32 + m * 16 + grp;
            #pragma unroll
            for (int g = 0; g < 2; g++) {
                const int p0 = (g * 8 + kk) * PSTR, p1 = p0 + 4 * PSTR;
                uint2 t;
                t = AHL[p0 + rb];     ah[m][g][0] = t.x; al[m][g][0] = t.y;
                t = AHL[p0 + rb + 8]; ah[m][g][1] = t.x; al[m][g][1] = t.y;
                t = AHL[p1 + rb];     ah[m][g][2] = t.x; al[m][g][2] = t.y;
                t = AHL[p1 + rb + 8]; ah[m][g][3] = t.x; al[m][g][3] = t.y;
            }
        }

        #pragma unroll
        for (int sp = 0; sp < 8; sp++) {
            float acc[2][2][4];
            #pragma unroll
            for (int m = 0; m < 2; m++)
                #pragma unroll
                for (int s = 0; s < 2; s++)
                    #pragma unroll
                    for (int q = 0; q < 4; q++) acc[m][s][q] = 0.f;

            #pragma unroll
            for (int g = 0; g < 2; g++) {
                const int p0 = (g * 8 + kk) * PSTR, p1 = p0 + 4 * PSTR;
                const int n_lo = sp * 8 + grp, n_hi = n_lo + 64;
                const uint2 b00 = BHL[p0 + n_lo];   // {b0h, b0l}
                const uint2 b01 = BHL[p1 + n_lo];   // {b1h, b1l}
                const uint2 b10 = BHL[p0 + n_hi];
                const uint2 b11 = BHL[p1 + n_hi];
                #pragma unroll
                for (int m = 0; m < 2; m++) {
                    mma_bf16(acc[m][0], ah[m][g], b00.x, b01.x);
                    mma_bf16(acc[m][0], al[m][g], b00.x, b01.x);
                    mma_bf16(acc[m][0], ah[m][g], b00.y, b01.y);
                    mma_bf16(acc[m][1], ah[m][g], b10.x, b11.x);
                    mma_bf16(acc[m][1], al[m][g], b10.x, b11.x);
                    mma_bf16(acc[m][1], ah[m][g], b10.y, b11.y);
                }
            }

            #pragma unroll
            for (int m = 0; m < 2; m++) {
                const size_t r0 = (size_t)(m0 + w * 32 + m * 16 + grp);
                #pragma unroll
                for (int s = 0; s < 2; s++) {
                    const int col = nb + sp * 8 + s * 64 + kk * 2;
                    __stcs(reinterpret_cast<float2*>(C + r0 * CD + col),
                           make_float2(acc[m][s][0], acc[m][s][1]));
                    __stcs(reinterpret_cast<float2*>(C + (r0 + 8) * CD + col),
                           make_float2(acc[m][s][2], acc[m][s][3]));
                }
            }
        }
    }
}

// ---------------------------------------------------------------------------
// m_t = A @ mu (tiny)
// ---------------------------------------------------------------------------
__global__ __launch_bounds__(256)
void m_kernel(const float* __restrict__ alpha,
              const float* __restrict__ mu,
              const float* __restrict__ asc,
              float* __restrict__ m)
{
    __shared__ float mu_s[NS * NC];
    __shared__ float a_s[16 * NS];
    __shared__ float scale_s[NS];

    const int tid = threadIdx.x;
    if (tid < NS) scale_s[tid] = log1pf(expf(asc[tid]));
    __syncthreads();

    for (int i = tid; i < NS * NC; i += 256) mu_s[i] = mu[i];

    const int bt0 = blockIdx.x * 16;
    for (int i = tid; i < 16 * NS; i += 256) {
        const int r = i / NS, j = i % NS;
        a_s[i] = alpha[(bt0 + r) * NS + j] * scale_s[j];
    }
    __syncthreads();

    for (int o = tid; o < 16 * NC; o += 256) {
        const int r = o / NC, c = o % NC;
        float s = 0.0f;
        #pragma unroll
        for (int j = 0; j < NS; j++) s = fmaf(a_s[r * NS + j], mu_s[j * NC + c], s);
        m[(size_t)(bt0 + r) * NC + c] = s;
    }
}

extern "C" void kernel_launch(void* const* d_in, const int* in_sizes, int n_in,
                              void* d_out, int out_size)
{
    const float* alpha = (const float*)d_in[0];   // [64,400,25]
    const float* mu    = (const float*)d_in[1];   // [25,80]
    const float* D     = (const float*)d_in[2];   // [25,80,80]
    const float* asc   = (const float*)d_in[3];   // [25]

    float* out   = (float*)d_out;
    float* m_out = out;                 // [64,400,80]
    float* c_out = out + (BT * NC);     // [64,400,80,80]

    m_kernel<<<BT / 16, 256>>>(alpha, mu, asc, m_out);
    tc_kernel<<<dim3(NXB, NYB), THREADS>>>(alpha, D, asc, c_out);
}